// round 16
// baseline (speedup 1.0000x reference)
#include <cuda_runtime.h>
#include <cuda_bf16.h>
#include <float.h>
#include <stdint.h>

#define Q      1024
#define D      512
#define NDATA  50000
#define NPAD   50048    // 391 * 128
#define NTILES 391      // 128-col tiles
#define NCAND  32

// ---------------- device scratch (allocation-free rule) ----------------
__device__ __nv_bfloat16 g_xb[(size_t)Q * D];                  // 1 MB
__device__ __nv_bfloat16 g_db[(size_t)NPAD * D];               // 51 MB (pad rows = 0)
__device__ unsigned long long g_part[(size_t)Q * NTILES * 10]; // 32 MB
__device__ int   g_cand[(size_t)Q * NCAND];
__device__ float g_d2[NPAD];
__device__ int   g_t_is_i64;

typedef unsigned long long ull;

__device__ __forceinline__ ull pack_key(float v, int idx) {
    unsigned int b = __float_as_uint(v);
    b = (b & 0x80000000u) ? ~b : (b | 0x80000000u);   // monotone float -> uint
    return ((ull)b << 32) | (unsigned int)idx;
}
__device__ __forceinline__ ull u64min(ull a, ull b) { return a < b ? a : b; }

__device__ __forceinline__ uint32_t smem_u32(const void* p) {
    uint32_t a;
    asm("{ .reg .u64 t; cvta.to.shared.u64 t, %1; cvt.u32.u64 %0, t; }" : "=r"(a) : "l"(p));
    return a;
}
__device__ __forceinline__ void ldsm_x4(unsigned* r, unsigned addr) {
    asm volatile("ldmatrix.sync.aligned.m8n8.x4.shared.b16 {%0,%1,%2,%3}, [%4];"
                 : "=r"(r[0]), "=r"(r[1]), "=r"(r[2]), "=r"(r[3]) : "r"(addr));
}
__device__ __forceinline__ void ldsm_x2(unsigned* r, unsigned addr) {
    asm volatile("ldmatrix.sync.aligned.m8n8.x2.shared.b16 {%0,%1}, [%2];"
                 : "=r"(r[0]), "=r"(r[1]) : "r"(addr));
}
__device__ __forceinline__ void mma16816(float* c, const unsigned* a, const unsigned* b) {
    asm volatile("mma.sync.aligned.m16n8k16.row.col.f32.bf16.bf16.f32 "
                 "{%0,%1,%2,%3}, {%4,%5,%6,%7}, {%8,%9}, {%0,%1,%2,%3};"
                 : "+f"(c[0]), "+f"(c[1]), "+f"(c[2]), "+f"(c[3])
                 : "r"(a[0]), "r"(a[1]), "r"(a[2]), "r"(a[3]), "r"(b[0]), "r"(b[1]));
}
__device__ __forceinline__ void cp_async16(uint32_t dst, const void* src) {
    asm volatile("cp.async.cg.shared.global [%0], [%1], 16;" :: "r"(dst), "l"(src));
}
#define CP_COMMIT() asm volatile("cp.async.commit_group;" ::: "memory")
#define CP_WAIT(n)  asm volatile("cp.async.wait_group %0;" :: "n"(n) : "memory")

// ---------------------------------------------------------------------------
// Kernel 0: targets dtype detect (int64 LE -> all odd words zero)
// ---------------------------------------------------------------------------
__global__ __launch_bounds__(256) void detect_dtype_kernel(const int* __restrict__ t32) {
    __shared__ int any_nz;
    if (threadIdx.x == 0) any_nz = 0;
    __syncthreads();
    int local = 0;
    for (int i = threadIdx.x; i < NDATA; i += 256) local |= t32[2 * i + 1];
    if (local) atomicOr(&any_nz, 1);
    __syncthreads();
    if (threadIdx.x == 0) g_t_is_i64 = (any_nz == 0) ? 1 : 0;
}

// ---------------------------------------------------------------------------
// Kernel 1 (fused): per-row norms (fp32) + fp32->bf16 data conversion.
// ---------------------------------------------------------------------------
__global__ __launch_bounds__(256) void norms_cvt_kernel(const float* __restrict__ data) {
    int gw   = (blockIdx.x * blockDim.x + threadIdx.x) >> 5;
    int lane = threadIdx.x & 31;
    if (gw >= NPAD) return;
    __nv_bfloat162* orow = reinterpret_cast<__nv_bfloat162*>(g_db + (size_t)gw * D);
    if (gw >= NDATA) {
        if (lane == 0) g_d2[gw] = 0.f;
        __nv_bfloat162 z = __floats2bfloat162_rn(0.f, 0.f);
#pragma unroll
        for (int j = 0; j < 4; ++j) {
            int e = lane + 32 * j;
            orow[2 * e] = z; orow[2 * e + 1] = z;
        }
        return;
    }
    const float4* row = reinterpret_cast<const float4*>(data + (size_t)gw * D);
    float s = 0.f;
#pragma unroll
    for (int j = 0; j < 4; ++j) {
        int e = lane + 32 * j;
        float4 v = row[e];
        s += v.x * v.x + v.y * v.y + v.z * v.z + v.w * v.w;
        orow[2 * e]     = __floats2bfloat162_rn(v.x, v.y);
        orow[2 * e + 1] = __floats2bfloat162_rn(v.z, v.w);
    }
#pragma unroll
    for (int off = 16; off > 0; off >>= 1) s += __shfl_down_sync(0xffffffffu, s, off);
    if (lane == 0) g_d2[gw] = s;
}

// ---------------------------------------------------------------------------
// Kernel 2: fp32 -> bf16 conversion of X
// ---------------------------------------------------------------------------
__global__ __launch_bounds__(256) void cvt_x_kernel(const float* __restrict__ X) {
    int i4 = blockIdx.x * blockDim.x + threadIdx.x;
    if (i4 >= Q * D / 4) return;
    float4 v = reinterpret_cast<const float4*>(X)[i4];
    __nv_bfloat162* o = reinterpret_cast<__nv_bfloat162*>(g_xb);
    o[2 * i4]     = __floats2bfloat162_rn(v.x, v.y);
    o[2 * i4 + 1] = __floats2bfloat162_rn(v.z, v.w);
}

// ---------------------------------------------------------------------------
// Kernel 3: bf16 HMMA score GEMM (128x128 block, K=512) + staged-scan top-10.
//   Main loop: 3-stage cp.async pipeline, one sync per K=32 chunk.
//   Epilogue: stage scores in smem (64-col halves, conflict-free stride 132),
//   one thread per query row scans serially with a 10-deep insertion list.
// ---------------------------------------------------------------------------
#define SROW   80                 // bytes per smem row (32 bf16 = 64B + 16B pad)
#define TILEB  (128 * SROW)       // 10240 B per tensor per stage
#define STAGEB (2 * TILEB)        // A + B
#define NSTAGE 3
#define DYN_SMEM (NSTAGE * STAGEB)  // 61440 B
#define SCSTRIDE 132              // floats; 132 % 32 == 4 -> conflict-free both phases

extern __shared__ unsigned char dynsmem[];

__global__ __launch_bounds__(256, 2) void mma_topk_kernel() {
    __shared__ float sd2[128];

    const int tid    = threadIdx.x;
    const int lane   = tid & 31;
    const int wid    = tid >> 5;
    const int warp_m = wid & 1;
    const int warp_n = wid >> 1;
    const int row0   = blockIdx.y * 128;
    const int col0   = blockIdx.x * 128;

    const uint32_t uS = smem_u32(dynsmem);

    if (tid < 128) sd2[tid] = g_d2[col0 + tid];

    auto fill = [&](int kc, int s) {
        const uint32_t uA = uS + s * STAGEB;
        const uint32_t uB = uA + TILEB;
#pragma unroll
        for (int i = 0; i < 4; ++i) {
            int idx = tid + i * 256;
            int isB = idx >> 9;
            int e   = idx & 511;
            int r   = e >> 2;
            int c16 = e & 3;
            uint32_t dst = (isB ? uB : uA) + r * SROW + c16 * 16;
            const __nv_bfloat16* src = isB
                ? (g_db + (size_t)(col0 + r) * D + kc * 32 + c16 * 8)
                : (g_xb + (size_t)(row0 + r) * D + kc * 32 + c16 * 8);
            cp_async16(dst, src);
        }
        CP_COMMIT();
    };

    float acc[4][4][4];
#pragma unroll
    for (int mi = 0; mi < 4; ++mi)
#pragma unroll
        for (int ni = 0; ni < 4; ++ni)
#pragma unroll
            for (int e = 0; e < 4; ++e) acc[mi][ni][e] = 0.f;

    const unsigned aoff = (warp_m * 64 + (lane & 15)) * SROW + (lane >> 4) * 16;
    const unsigned boff = (warp_n * 32 + (lane & 7)) * SROW + ((lane >> 3) & 1) * 16;

    fill(0, 0);
    fill(1, 1);
    for (int c = 0; c < 16; ++c) {
        const int s = c % NSTAGE;
        if (c < 15) { CP_WAIT(1); } else { CP_WAIT(0); }
        __syncthreads();

        const uint32_t uA = uS + s * STAGEB;
        const uint32_t uB = uA + TILEB;
#pragma unroll
        for (int kk = 0; kk < 2; ++kk) {
            unsigned a[4][4], b[4][2];
#pragma unroll
            for (int mi = 0; mi < 4; ++mi)
                ldsm_x4(a[mi], uA + aoff + mi * 16 * SROW + kk * 32);
#pragma unroll
            for (int ni = 0; ni < 4; ++ni)
                ldsm_x2(b[ni], uB + boff + ni * 8 * SROW + kk * 32);
#pragma unroll
            for (int mi = 0; mi < 4; ++mi)
#pragma unroll
                for (int ni = 0; ni < 4; ++ni)
                    mma16816(acc[mi][ni], a[mi], b[ni]);
        }
        if (c + 2 < 16) fill(c + 2, (c + 2) % NSTAGE);
    }

    // ---- staged-scan epilogue ----
    float* sc = reinterpret_cast<float*>(dynsmem);   // sc[col][row], stride 132
    const int g    = lane >> 2;
    const int qoff = lane & 3;

    float val[10];
    int   vidx[10];
#pragma unroll
    for (int i = 0; i < 10; ++i) { val[i] = FLT_MAX; vidx[i] = 0x7fffffff; }

#pragma unroll
    for (int h = 0; h < 2; ++h) {     // column halves 0-63, 64-127
        __syncthreads();              // previous half's reads (or MMA loop) done
        if ((warp_n >> 1) == h) {
            const int colbase = (warp_n & 1) * 32;
#pragma unroll
            for (int mi = 0; mi < 4; ++mi)
#pragma unroll
                for (int hp = 0; hp < 2; ++hp) {
                    const int row = warp_m * 64 + mi * 16 + g + 8 * hp;
#pragma unroll
                    for (int ni = 0; ni < 4; ++ni)
#pragma unroll
                        for (int j = 0; j < 2; ++j) {
                            const int ch = colbase + ni * 8 + qoff * 2 + j;
                            sc[ch * SCSTRIDE + row] =
                                fmaf(-2.f, acc[mi][ni][2 * hp + j], sd2[64 * h + ch]);
                        }
                }
        }
        __syncthreads();
        if (tid < 128) {
            const int cb = col0 + 64 * h;
#pragma unroll 8
            for (int cidx = 0; cidx < 64; ++cidx) {
                float f = sc[cidx * SCSTRIDE + tid];
                int col = cb + cidx;
                if (f < val[9] && col < NDATA) {
                    int p = 9;
                    while (p > 0 && f < val[p - 1]) {
                        val[p] = val[p - 1]; vidx[p] = vidx[p - 1]; --p;
                    }
                    val[p] = f; vidx[p] = col;
                }
            }
        }
    }

    if (tid < 128) {
        ull* dst = g_part + ((size_t)(row0 + tid) * NTILES + blockIdx.x) * 10;
#pragma unroll
        for (int i = 0; i < 10; ++i) dst[i] = pack_key(val[i], vidx[i]);
    }
}

// ---------------------------------------------------------------------------
// Kernel 4: merge 391 sorted 10-lists -> top-32 candidates per query.
// ---------------------------------------------------------------------------
__global__ __launch_bounds__(256) void merge_cand_kernel() {
    const int q   = blockIdx.x;
    const int tid = threadIdx.x;
    const ull* part = g_part + (size_t)q * NTILES * 10;

    ull L[NCAND];
#pragma unroll
    for (int i = 0; i < NCAND; ++i) L[i] = ~0ull;

    for (int t = tid; t < NTILES; t += 256) {
        const ull* tl = part + t * 10;
#pragma unroll
        for (int s = 0; s < 10; ++s) {
            ull key = tl[s];
            if (key >= L[NCAND - 1]) break;
            L[NCAND - 1] = key;
#pragma unroll
            for (int p = NCAND - 1; p > 0; --p) {
                if (L[p] < L[p - 1]) { ull x = L[p]; L[p] = L[p - 1]; L[p - 1] = x; }
            }
        }
    }

    __shared__ ull sl[256][NCAND];
#pragma unroll
    for (int i = 0; i < NCAND; ++i) sl[tid][i] = L[i];
    __syncthreads();

    for (int Lv = 128; Lv >= 1; Lv >>= 1) {
        if (tid < Lv) {
            const ull* A = sl[tid];
            const ull* B = sl[tid + Lv];
            ull outm[NCAND];
            int ia = 0, ib = 0;
#pragma unroll
            for (int i = 0; i < NCAND; ++i) {
                ull av = A[ia], bv = B[ib];
                if (av <= bv) { outm[i] = av; ++ia; }
                else          { outm[i] = bv; ++ib; }
            }
#pragma unroll
            for (int i = 0; i < NCAND; ++i) sl[tid][i] = outm[i];
        }
        __syncthreads();
    }

    if (tid < NCAND) g_cand[q * NCAND + tid] = (int)(sl[0][tid] & 0xffffffffu);
}

// ---------------------------------------------------------------------------
// Kernel 5: exact fp32 rescore of 32 candidates + top-10 + mode.
// ---------------------------------------------------------------------------
__global__ __launch_bounds__(256) void rescore_kernel(const float* __restrict__ X,
                                                      const float* __restrict__ data,
                                                      const int* __restrict__ t32,
                                                      float* __restrict__ out) {
    const int q    = blockIdx.x;
    const int tid  = threadIdx.x;
    const int lane = tid & 31;
    const int wid  = tid >> 5;

    __shared__ float4 xq[128];
    __shared__ ull keys[NCAND];

    if (tid < 128) xq[tid] = reinterpret_cast<const float4*>(X + (size_t)q * D)[tid];
    __syncthreads();

#pragma unroll
    for (int rr = 0; rr < NCAND / 8; ++rr) {
        int ci = wid + rr * 8;
        const int c = g_cand[q * NCAND + ci];
        const float4* drow = reinterpret_cast<const float4*>(data + (size_t)c * D);
        float dot = 0.f;
#pragma unroll
        for (int u = 0; u < 4; ++u) {
            float4 dv = drow[lane * 4 + u];
            float4 xv = xq[lane * 4 + u];
            dot += dv.x * xv.x + dv.y * xv.y + dv.z * xv.z + dv.w * xv.w;
        }
#pragma unroll
        for (int off = 16; off > 0; off >>= 1) dot += __shfl_down_sync(0xffffffffu, dot, off);
        if (lane == 0) keys[ci] = pack_key(fmaf(-2.f, dot, g_d2[c]), c);
    }
    __syncthreads();

    if (wid == 0) {
        ull k0 = keys[lane];               // NCAND == 32
        ull top[10];
#pragma unroll
        for (int rr = 0; rr < 10; ++rr) {
            ull m = k0;
#pragma unroll
            for (int off = 16; off > 0; off >>= 1)
                m = u64min(m, __shfl_xor_sync(0xffffffffu, m, off));
            top[rr] = m;
            if (k0 == m) k0 = ~0ull;
        }
        if (lane == 0) {
            const int is64 = g_t_is_i64;
            int lab[10];
#pragma unroll
            for (int i = 0; i < 10; ++i) {
                int w = (int)(top[i] & 0xffffffffu);
                lab[i] = is64 ? t32[2 * w] : t32[w];
            }
            int bestLab = 0x7fffffff, bestCnt = 0;
#pragma unroll
            for (int i = 0; i < 10; ++i) {
                int c = 0;
#pragma unroll
                for (int j = 0; j < 10; ++j) c += (lab[j] == lab[i]) ? 1 : 0;
                if (c > bestCnt || (c == bestCnt && lab[i] < bestLab)) { bestCnt = c; bestLab = lab[i]; }
            }
            out[q] = (float)bestLab;
        }
    }
}

// ---------------------------------------------------------------------------
extern "C" void kernel_launch(void* const* d_in, const int* in_sizes, int n_in,
                              void* d_out, int out_size) {
    const float* X    = nullptr;
    const float* data = nullptr;
    const int*   t32  = nullptr;
    for (int i = 0; i < n_in; ++i) {
        if (in_sizes[i] == Q * D)            X    = (const float*)d_in[i];
        else if (in_sizes[i] == NDATA * D)   data = (const float*)d_in[i];
        else if (in_sizes[i] == NDATA)       t32  = (const int*)d_in[i];
    }
    float* out = (float*)d_out;
    (void)out_size;

    cudaFuncSetAttribute(mma_topk_kernel,
                         cudaFuncAttributeMaxDynamicSharedMemorySize, DYN_SMEM);

    detect_dtype_kernel<<<1, 256>>>(t32);
    norms_cvt_kernel<<<(NPAD * 32 + 255) / 256, 256>>>(data);
    cvt_x_kernel<<<(Q * D / 4 + 255) / 256, 256>>>(X);

    dim3 grid(NTILES, Q / 128);   // 391 x 8
    mma_topk_kernel<<<grid, 256, DYN_SMEM>>>();

    merge_cand_kernel<<<Q, 256>>>();
    rescore_kernel<<<Q, 256>>>(X, data, t32, out);
}